// round 7
// baseline (speedup 1.0000x reference)
#include <cuda_runtime.h>
#include <cstdint>

// Fixed problem shape
#define NB 8
#define HW (640*640)              // 409600 px/image
#define NL 33
#define NREP 8                    // accumulator replicas (L2 slice spreading)
#define TPB 256
#define NBLK (148*4)              // 592 blocks: guaranteed co-resident wave 1
#define TILES_PER_BATCH (HW/128)  // warp-tile = 128 px (lane handles 4, float4)
#define NTILES (NB*TILES_PER_BATCH) // 25600
#define FULLM 0xFFFFFFFFu

// 256B-aligned: consecutive hot accumulators differ in addr bits >=8 -> spread
// across L2 slices (bit 7 transparent in the slice hash).
struct alignas(256) Accum {
    float4   sums;     // kernel-masked embedding sums
    unsigned cnt;      // (cnt_i << 16) | cnt_k
    float    pad[59];
};

// Zero-initialized at load; last block restores zeros -> graph replays OK.
__device__ Accum    g_acc[NREP][NB][NL];
__device__ unsigned g_t1, g_t2, g_done1, g_done2;
__device__ float    g_scalar;

__device__ __forceinline__ void red_add_v4f(float4* p, float a, float b, float c, float d) {
    asm volatile("red.global.add.v4.f32 [%0], {%1, %2, %3, %4};"
                 :: "l"(p), "f"(a), "f"(b), "f"(c), "f"(d) : "memory");
}
__device__ __forceinline__ void red_add_u32(unsigned* p, unsigned v) {
    asm volatile("red.global.add.u32 [%0], %1;" :: "l"(p), "r"(v) : "memory");
}
__device__ __forceinline__ void red_add_f32(float* p, float v) {
    asm volatile("red.global.add.f32 [%0], %1;" :: "l"(p), "f"(v) : "memory");
}
__device__ __forceinline__ float sqrt_approx(float x) {
    float r; asm("sqrt.approx.f32 %0, %1;" : "=f"(r) : "f"(x)); return r;
}

__global__ __launch_bounds__(TPB, 4) void k_fused(
    const float* __restrict__ emb, const int* __restrict__ inst,
    const float* __restrict__ kern, const float* __restrict__ tmk,
    float* __restrict__ out)
{
    __shared__ float4 smean[NB][NL];
    __shared__ float  sw[NB][NL];
    __shared__ float  sred[TPB];
    __shared__ int    slast;

    int tid = threadIdx.x;
    unsigned lane = tid & 31u;
    int wid = tid >> 5;
    unsigned rep = (unsigned)(blockIdx.x * (TPB / 32) + wid) & (NREP - 1);

    // ================= PHASE 1: masked segment sums + counts =================
    // Warp-level dynamic tickets; next ticket's atomicAdd overlaps processing.
    unsigned traw = 0;
    if (lane == 0) traw = atomicAdd(&g_t1, 1u);
    unsigned t = __shfl_sync(FULLM, traw, 0);
    while (t < NTILES) {
        if (lane == 0) traw = atomicAdd(&g_t1, 1u);

        int b  = (int)(t / TILES_PER_BATCH);
        int r  = (int)t - b * TILES_PER_BATCH;
        int px = r * 128 + (int)lane * 4;
        int base = b * HW + px;

        int4   iv = *reinterpret_cast<const int4*>(inst + base);
        float4 tv = *reinterpret_cast<const float4*>(tmk + base);
        float4 kv = *reinterpret_cast<const float4*>(kern + base);
        const int*   ivp = reinterpret_cast<const int*>(&iv);
        const float* tvp = reinterpret_cast<const float*>(&tv);
        const float* kvp = reinterpret_cast<const float*>(&kv);

        int  li[4]; bool kk[4]; bool anyk = false;
#pragma unroll
        for (int j = 0; j < 4; j++) {
            int l = (tvp[j] > 0.5f) ? ivp[j] : 0;
            if ((unsigned)l >= NL) l = 0;
            li[j] = l;
            kk[j] = (kvp[j] > 0.5f) && (l != 0);
            anyk |= kk[j];
        }

        float4 e0 = make_float4(0.f,0.f,0.f,0.f), e1 = e0, e2 = e0, e3 = e0;
        if (anyk) {   // emb only feeds kernel-masked sums (~41% of lanes skip)
            const float* eb = emb + (size_t)b * 4 * HW + px;
            e0 = *reinterpret_cast<const float4*>(eb);
            e1 = *reinterpret_cast<const float4*>(eb + HW);
            e2 = *reinterpret_cast<const float4*>(eb + 2 * HW);
            e3 = *reinterpret_cast<const float4*>(eb + 3 * HW);
        }
        const float* c0 = reinterpret_cast<const float*>(&e0);
        const float* c1 = reinterpret_cast<const float*>(&e1);
        const float* c2 = reinterpret_cast<const float*>(&e2);
        const float* c3 = reinterpret_cast<const float*>(&e3);

#pragma unroll
        for (int j = 0; j < 4; j++) {
            unsigned mm = __match_any_sync(FULLM, li[j]);   // warp-aggregate cnts
            unsigned kb = __ballot_sync(FULLM, kk[j]);
            if (li[j] != 0) {
                Accum* a = &g_acc[rep][b][li[j]];
                if ((unsigned)(__ffs(mm) - 1) == lane)
                    red_add_u32(&a->cnt, ((unsigned)__popc(mm) << 16)
                                         | (unsigned)__popc(mm & kb));
                if (kk[j])
                    red_add_v4f(&a->sums, c0[j], c1[j], c2[j], c3[j]);
            }
        }
        t = __shfl_sync(FULLM, traw, 0);
    }

    // ================= grid barrier =================
    __syncthreads();
    if (tid == 0) {
        __threadfence();                 // publish REDs
        atomicAdd(&g_done1, 1u);
        while (*(volatile unsigned*)&g_done1 < NBLK) __nanosleep(64);
        __threadfence();                 // acquire
    }
    __syncthreads();

    // ================= means for ALL batches, once per block =================
    for (int i = tid; i < NB * NL; i += TPB) {
        int b = i / NL, l = i - b * NL;
        float sx = 0.f, sy = 0.f, sz = 0.f, sww = 0.f;
        unsigned c = 0u;
#pragma unroll
        for (int rr = 0; rr < NREP; rr++) {
            const Accum& a = g_acc[rr][b][l];
            sx += a.sums.x; sy += a.sums.y; sz += a.sums.z; sww += a.sums.w;
            c += a.cnt;
        }
        float cnt_k = (float)(c & 0xFFFFu);
        float cnt_i = (float)(c >> 16);
        float inv = (l == 0) ? 0.f : (1.f / fmaxf(cnt_k, 1.f));
        smean[b][l] = make_float4(sx * inv, sy * inv, sz * inv, sww * inv);
        sw[b][l] = (l == 0) ? 0.f : (1.f / (32.f * fmaxf(cnt_i, 1.f)));
    }
    __syncthreads();

    // ================= PHASE 2: per-pixel loss (L2-resident reads) ===========
    float acc = 0.f;
    if (lane == 0) traw = atomicAdd(&g_t2, 1u);
    t = __shfl_sync(FULLM, traw, 0);
    while (t < NTILES) {
        if (lane == 0) traw = atomicAdd(&g_t2, 1u);

        int b  = (int)(t / TILES_PER_BATCH);
        int r  = (int)t - b * TILES_PER_BATCH;
        int px = r * 128 + (int)lane * 4;
        int base = b * HW + px;

        int4   iv = *reinterpret_cast<const int4*>(inst + base);
        float4 tv = *reinterpret_cast<const float4*>(tmk + base);
        const float* eb = emb + (size_t)b * 4 * HW + px;
        float4 e0 = *reinterpret_cast<const float4*>(eb);
        float4 e1 = *reinterpret_cast<const float4*>(eb + HW);
        float4 e2 = *reinterpret_cast<const float4*>(eb + 2 * HW);
        float4 e3 = *reinterpret_cast<const float4*>(eb + 3 * HW);

        const int*   ivp = reinterpret_cast<const int*>(&iv);
        const float* tvp = reinterpret_cast<const float*>(&tv);
        const float* c0  = reinterpret_cast<const float*>(&e0);
        const float* c1  = reinterpret_cast<const float*>(&e1);
        const float* c2  = reinterpret_cast<const float*>(&e2);
        const float* c3  = reinterpret_cast<const float*>(&e3);

#pragma unroll
        for (int j = 0; j < 4; j++) {
            int li = (tvp[j] > 0.5f) ? ivp[j] : 0;
            if ((unsigned)li >= NL) li = 0;
            float4 m = smean[b][li];
            float wv = sw[b][li];                 // w[0]=0: branchless mask
            float dx = c0[j] - m.x, dy = c1[j] - m.y;
            float dz = c2[j] - m.z, dw = c3[j] - m.w;
            float s  = dx*dx + dy*dy + dz*dz + dw*dw;
            float tt = fmaxf(sqrt_approx(s) - 0.5f, 0.f);   // DELTA_V = 0.5
            acc = fmaf(wv, __logf(fmaf(tt, tt, 1.f)), acc);
        }
        t = __shfl_sync(FULLM, traw, 0);
    }

#pragma unroll
    for (int off = 16; off; off >>= 1)
        acc += __shfl_down_sync(FULLM, acc, off);
    if (lane == 0) red_add_f32(&g_scalar, acc);   // one RED per warp

    __syncthreads();
    if (tid == 0) {
        __threadfence();
        slast = (atomicAdd(&g_done2, 1u) == (unsigned)(NBLK - 1)) ? 1 : 0;
    }
    __syncthreads();
    if (!slast) return;

    // ================= epilogue (last block): l_dis + l_reg ==================
    __threadfence();
    float a2 = 0.f;
    for (int i = tid; i < NB * 32; i += TPB) {          // l_reg
        int bb = i >> 5, l = (i & 31) + 1;
        float4 m = smean[bb][l];
        float n = sqrtf(m.x*m.x + m.y*m.y + m.z*m.z + m.w*m.w);
        a2 += logf(n + 1.f) * (0.001f / 33.0f);
    }
    for (int idx = tid; idx < NB * 32 * 32; idx += TPB) {   // l_dis, i != j
        int bb = idx >> 10, rr = idx & 1023, i = rr >> 5, j = rr & 31;
        if (i != j) {
            float4 mi = smean[bb][i + 1], mj = smean[bb][j + 1];
            float dx = mi.x - mj.x, dy = mi.y - mj.y;
            float dz = mi.z - mj.z, dw = mi.w - mj.w;
            float pd = sqrtf(dx*dx + dy*dy + dz*dz + dw*dw);
            float tt = fmaxf(3.0f - pd, 0.f);               // 2*DELTA_D
            a2 += logf(fmaf(tt, tt, 1.f)) * (1.0f / 992.0f);
        }
    }
    sred[tid] = a2;
    __syncthreads();
    for (int s = TPB / 2; s > 0; s >>= 1) {
        if (tid < s) sred[tid] += sred[tid + s];
        __syncthreads();
    }
    if (tid == 0) {
        float S = *(volatile float*)&g_scalar;      // l_agg (weights folded in)
        out[0] = (S + sred[0]) * (1.0f / NB);       // LOSS_WEIGHT = 1
    }

    // ---- restore zeros for next graph replay ----
    float4 z4 = make_float4(0.f, 0.f, 0.f, 0.f);
    Accum* aa = &g_acc[0][0][0];
    for (int i = tid; i < NREP * NB * NL; i += TPB) {
        aa[i].sums = z4;
        aa[i].cnt  = 0u;
    }
    if (tid == 0) {
        g_t1 = 0u; g_t2 = 0u; g_done1 = 0u; g_done2 = 0u; g_scalar = 0.f;
    }
}

// ---------------- launch: ONE persistent kernel ------------------------------
extern "C" void kernel_launch(void* const* d_in, const int* in_sizes, int n_in,
                              void* d_out, int out_size) {
    (void)in_sizes; (void)n_in; (void)out_size;
    const float* emb  = (const float*)d_in[0];
    const int*   inst = (const int*)d_in[1];
    const float* kern = (const float*)d_in[2];
    const float* tmk  = (const float*)d_in[3];
    float* out = (float*)d_out;

    k_fused<<<NBLK, TPB>>>(emb, inst, kern, tmk, out);
}

// round 8
// speedup vs baseline: 1.6079x; 1.6079x over previous
#include <cuda_runtime.h>
#include <cstdint>

// Fixed problem shape
#define NB 8
#define HW (640*640)        // 409600
#define NL 33
#define NREP 8              // accumulator replicas (L2 slice spreading)
#define TPB 256
#define PPT 4
#define PIX_PER_BLOCK (TPB*PPT)              // 1024
#define BLOCKS_PER_BATCH (HW/PIX_PER_BLOCK)  // 400 exact
#define GRID_MAIN (NB*BLOCKS_PER_BATCH)      // 3200
#define FULLM 0xFFFFFFFFu

// 256B-aligned: consecutive hot accumulators differ in addr bits >=8 -> spread
// across L2 slices (bit 7 transparent in the slice hash).
struct alignas(256) Accum {
    float4   sums;     // kernel-masked embedding sums
    unsigned cnt;      // (cnt_i << 16) | cnt_k
    float    pad[59];
};

// Zero-initialized at load; k_mean re-zeroes g_acc each launch; the phase2
// epilogue resets its own ticket -> graph replays are self-consistent.
__device__ Accum    g_acc[NREP][NB][NL];
__device__ float4   g_mean[NB][NL];
__device__ float    g_w[NB][NL];
__device__ unsigned g_lab[NB * HW / 4];   // packed per-pixel labels (4 x u8)
__device__ float    g_scalar;
__device__ unsigned g_done;

__device__ __forceinline__ void red_add_v4f(float4* p, float a, float b, float c, float d) {
    asm volatile("red.global.add.v4.f32 [%0], {%1, %2, %3, %4};"
                 :: "l"(p), "f"(a), "f"(b), "f"(c), "f"(d) : "memory");
}
__device__ __forceinline__ void red_add_u32(unsigned* p, unsigned v) {
    asm volatile("red.global.add.u32 [%0], %1;" :: "l"(p), "r"(v) : "memory");
}
__device__ __forceinline__ void red_add_f32(float* p, float v) {
    asm volatile("red.global.add.f32 [%0], %1;" :: "l"(p), "f"(v) : "memory");
}
__device__ __forceinline__ float sqrt_approx(float x) {
    float r; asm("sqrt.approx.f32 %0, %1;" : "=f"(r) : "f"(x)); return r;
}

// ---------------- K1: masked segment sums + counts + label cache -------------
__global__ __launch_bounds__(TPB) void k_phase1(
    const float* __restrict__ emb, const int* __restrict__ inst,
    const float* __restrict__ kern, const float* __restrict__ tmk) {
    int blk = blockIdx.x;
    int b   = blk / BLOCKS_PER_BATCH;
    unsigned rep = (unsigned)blk & (NREP - 1);
    int p   = (blk - b * BLOCKS_PER_BATCH) * PIX_PER_BLOCK + threadIdx.x * PPT;
    int base = b * HW + p;
    unsigned lane = threadIdx.x & 31u;

    int4   iv = *reinterpret_cast<const int4*>(inst + base);
    float4 tv = *reinterpret_cast<const float4*>(tmk + base);
    float4 kv = *reinterpret_cast<const float4*>(kern + base);
    const int*   ivp = reinterpret_cast<const int*>(&iv);
    const float* tvp = reinterpret_cast<const float*>(&tv);
    const float* kvp = reinterpret_cast<const float*>(&kv);

    int  li[PPT]; bool kk[PPT]; bool anyk = false;
#pragma unroll
    for (int j = 0; j < PPT; j++) {
        int l = (tvp[j] > 0.5f) ? ivp[j] : 0;
        if ((unsigned)l >= NL) l = 0;
        li[j] = l;
        kk[j] = (kvp[j] > 0.5f) && (l != 0);
        anyk |= kk[j];
    }

    // Cache labels for phase 2 (replaces re-reading inst+tmk there).
    g_lab[base >> 2] = (unsigned)li[0] | ((unsigned)li[1] << 8)
                     | ((unsigned)li[2] << 16) | ((unsigned)li[3] << 24);

    // emb only feeds kernel-masked sums: skip loads when no pixel qualifies.
    float4 e0 = make_float4(0.f,0.f,0.f,0.f), e1 = e0, e2 = e0, e3 = e0;
    if (anyk) {
        const float* eb = emb + (size_t)b * 4 * HW + p;
        e0 = *reinterpret_cast<const float4*>(eb);
        e1 = *reinterpret_cast<const float4*>(eb + HW);
        e2 = *reinterpret_cast<const float4*>(eb + 2 * HW);
        e3 = *reinterpret_cast<const float4*>(eb + 3 * HW);
    }
    const float* c0 = reinterpret_cast<const float*>(&e0);
    const float* c1 = reinterpret_cast<const float*>(&e1);
    const float* c2 = reinterpret_cast<const float*>(&e2);
    const float* c3 = reinterpret_cast<const float*>(&e3);

#pragma unroll
    for (int j = 0; j < PPT; j++) {
        unsigned mm = __match_any_sync(FULLM, li[j]);   // warp-aggregate counts
        unsigned kb = __ballot_sync(FULLM, kk[j]);
        if (li[j] != 0) {
            Accum* a = &g_acc[rep][b][li[j]];
            if ((unsigned)(__ffs(mm) - 1) == lane)
                red_add_u32(&a->cnt, ((unsigned)__popc(mm) << 16)
                                     | (unsigned)__popc(mm & kb));
            if (kk[j])
                red_add_v4f(&a->sums, c0[j], c1[j], c2[j], c3[j]);
        }
    }
}

// ---------------- K2: means + weights; re-zero accumulators ------------------
__global__ void k_mean() {
    int i = blockIdx.x * blockDim.x + threadIdx.x;
    if (i == 0) g_scalar = 0.f;
    if (i >= NB * NL) return;
    int b = i / NL, l = i - b * NL;
    float sx = 0.f, sy = 0.f, sz = 0.f, sww = 0.f;
    unsigned c = 0u;
    float4 z4 = make_float4(0.f, 0.f, 0.f, 0.f);
#pragma unroll
    for (int r = 0; r < NREP; r++) {
        Accum& a = g_acc[r][b][l];
        sx += a.sums.x; sy += a.sums.y; sz += a.sums.z; sww += a.sums.w;
        c += a.cnt;
        a.sums = z4; a.cnt = 0u;        // reset for next graph replay
    }
    float cnt_k = (float)(c & 0xFFFFu);
    float cnt_i = (float)(c >> 16);
    float inv = (l == 0) ? 0.f : (1.f / fmaxf(cnt_k, 1.f));
    g_mean[b][l] = make_float4(sx * inv, sy * inv, sz * inv, sww * inv);
    g_w[b][l]    = (l == 0) ? 0.f : (1.f / (32.f * fmaxf(cnt_i, 1.f)));
}

// ---------------- K3: per-pixel loss (L2-hot) + epilogue ---------------------
__global__ __launch_bounds__(TPB) void k_phase2(
    const float* __restrict__ emb, float* __restrict__ out) {
    __shared__ float4 smean[NL];
    __shared__ float  swt[NL];
    __shared__ float  swred[8];
    __shared__ int    slast;

    int blk = blockIdx.x;
    int b   = blk / BLOCKS_PER_BATCH;
    int tid = threadIdx.x;
    if (tid < NL) { smean[tid] = g_mean[b][tid]; swt[tid] = g_w[b][tid]; }
    __syncthreads();

    int p    = (blk - b * BLOCKS_PER_BATCH) * PIX_PER_BLOCK + tid * PPT;
    int base = b * HW + p;

    unsigned lab = g_lab[base >> 2];
    const float* eb = emb + (size_t)b * 4 * HW + p;
    float4 e0 = *reinterpret_cast<const float4*>(eb);
    float4 e1 = *reinterpret_cast<const float4*>(eb + HW);
    float4 e2 = *reinterpret_cast<const float4*>(eb + 2 * HW);
    float4 e3 = *reinterpret_cast<const float4*>(eb + 3 * HW);
    const float* c0 = reinterpret_cast<const float*>(&e0);
    const float* c1 = reinterpret_cast<const float*>(&e1);
    const float* c2 = reinterpret_cast<const float*>(&e2);
    const float* c3 = reinterpret_cast<const float*>(&e3);

    float acc = 0.f;   // branchless: w[0]=0 kills unmasked pixels
#pragma unroll
    for (int j = 0; j < PPT; j++) {
        int li = (int)((lab >> (8 * j)) & 0xFFu);
        float4 m = smean[li];
        float wv = swt[li];
        float dx = c0[j] - m.x, dy = c1[j] - m.y;
        float dz = c2[j] - m.z, dw = c3[j] - m.w;
        float s  = dx*dx + dy*dy + dz*dz + dw*dw;
        float tt = fmaxf(sqrt_approx(s) - 0.5f, 0.f);     // DELTA_V = 0.5
        acc = fmaf(wv, __logf(fmaf(tt, tt, 1.f)), acc);
    }

    // Block reduction -> ONE global RED per block (3200 total).
#pragma unroll
    for (int off = 16; off; off >>= 1)
        acc += __shfl_down_sync(FULLM, acc, off);
    if ((tid & 31) == 0) swred[tid >> 5] = acc;
    __syncthreads();
    if (tid == 0) {
        float s2 = 0.f;
#pragma unroll
        for (int w = 0; w < 8; w++) s2 += swred[w];
        red_add_f32(&g_scalar, s2);
        __threadfence();
        slast = (atomicAdd(&g_done, 1u) == (unsigned)(GRID_MAIN - 1)) ? 1 : 0;
    }
    __syncthreads();
    if (!slast) return;

    // ---------- epilogue (last block): l_dis + l_reg, write out --------------
    __threadfence();
    __shared__ float sred2[TPB];
    float a2 = 0.f;
    for (int i = tid; i < NB * 32; i += TPB) {            // l_reg
        int bb = i >> 5, l = (i & 31) + 1;
        float4 m = g_mean[bb][l];
        float n = sqrtf(m.x*m.x + m.y*m.y + m.z*m.z + m.w*m.w);
        a2 += logf(n + 1.f) * (0.001f / 33.0f);
    }
    for (int idx = tid; idx < NB * 32 * 32; idx += TPB) { // l_dis, i != j
        int bb = idx >> 10, rr = idx & 1023, i = rr >> 5, j = rr & 31;
        if (i != j) {
            float4 mi = g_mean[bb][i + 1], mj = g_mean[bb][j + 1];
            float dx = mi.x - mj.x, dy = mi.y - mj.y;
            float dz = mi.z - mj.z, dw = mi.w - mj.w;
            float pd = sqrtf(dx*dx + dy*dy + dz*dz + dw*dw);
            float tt = fmaxf(3.0f - pd, 0.f);             // 2*DELTA_D
            a2 += logf(fmaf(tt, tt, 1.f)) * (1.0f / 992.0f);
        }
    }
    sred2[tid] = a2;
    __syncthreads();
    for (int s = TPB / 2; s > 0; s >>= 1) {
        if (tid < s) sred2[tid] += sred2[tid + s];
        __syncthreads();
    }
    if (tid == 0) {
        float S = *(volatile float*)&g_scalar;   // l_agg (weights folded in)
        out[0] = (S + sred2[0]) * (1.0f / NB);   // LOSS_WEIGHT = 1
        g_done = 0u;                             // reset ticket for next replay
    }
}

// ---------------- launch: 3 kernels ------------------------------------------
extern "C" void kernel_launch(void* const* d_in, const int* in_sizes, int n_in,
                              void* d_out, int out_size) {
    (void)in_sizes; (void)n_in; (void)out_size;
    const float* emb  = (const float*)d_in[0];
    const int*   inst = (const int*)d_in[1];
    const float* kern = (const float*)d_in[2];
    const float* tmk  = (const float*)d_in[3];
    float* out = (float*)d_out;

    k_phase1<<<GRID_MAIN, TPB>>>(emb, inst, kern, tmk);
    k_mean  <<<2, 160>>>();
    k_phase2<<<GRID_MAIN, TPB>>>(emb, out);
}